// round 1
// baseline (speedup 1.0000x reference)
#include <cuda_runtime.h>

// Problem constants
#define B    64
#define T    512
#define DIN  256
#define H    512
#define G    2048   // 4*H

// Recurrence kernel config
#define NCTA      128
#define RTHREADS  256
#define KCH       128          // h-chunk staged per inner pass
#define WS_STRIDE 516          // 512 + 4 (bank spread, 16B aligned)
#define HS_STRIDE 132          // 128 + 4 (bank spread, 16B aligned)
#define GB_STRIDE 66
#define RECUR_SMEM ((16*WS_STRIDE + 64*HS_STRIDE + 16*GB_STRIDE) * 4)

typedef unsigned long long u64;

// ------------------------- device scratch -------------------------
__device__ float g_Wih0[G * DIN];
__device__ float g_Whh0[G * H];
__device__ float g_Wih1[G * H];
__device__ float g_Whh1[G * H];
__device__ float g_bias0[G];
__device__ float g_bias1[G];
__device__ float g_xW[(size_t)T * B * G];     // per-timestep input projection [t*B+b][G]
__device__ float g_hseq[(size_t)T * B * H];   // layer0 hidden sequence [t*B+b][H]
__device__ float g_h[2][B * H];               // double-buffered hidden state
__device__ unsigned int g_bar;                // grid barrier counter

// ------------------------- helpers -------------------------
__device__ __forceinline__ u64 f2pack(float x, float y) {
    u64 r; asm("mov.b64 %0, {%1, %2};" : "=l"(r) : "f"(x), "f"(y)); return r;
}
__device__ __forceinline__ float2 f2unpack(u64 v) {
    float2 r; asm("mov.b64 {%0, %1}, %2;" : "=f"(r.x), "=f"(r.y) : "l"(v)); return r;
}
__device__ __forceinline__ void ffma2(u64& d, u64 a, u64 b) {
    asm("fma.rn.f32x2 %0, %1, %2, %0;" : "+l"(d) : "l"(a), "l"(b));
}
__device__ __forceinline__ float sigmf(float x) {
    return 1.0f / (1.0f + __expf(-x));
}

// ------------------------- prep: masked weights + fused biases -------------------------
__global__ void prep_kernel(const float* Wih0, const float* mih0,
                            const float* Whh0, const float* mhh0,
                            const float* bih0, const float* bhh0,
                            const float* Wih1, const float* mih1,
                            const float* Whh1, const float* mhh1,
                            const float* bih1, const float* bhh1)
{
    int idx0 = blockIdx.x * blockDim.x + threadIdx.x;
    int stride = gridDim.x * blockDim.x;
    for (int i = idx0; i < G * DIN; i += stride) g_Wih0[i] = Wih0[i] * mih0[i];
    for (int i = idx0; i < G * H;  i += stride) g_Whh0[i] = Whh0[i] * mhh0[i];
    for (int i = idx0; i < G * H;  i += stride) g_Wih1[i] = Wih1[i] * mih1[i];
    for (int i = idx0; i < G * H;  i += stride) g_Whh1[i] = Whh1[i] * mhh1[i];
    for (int i = idx0; i < G;      i += stride) {
        g_bias0[i] = bih0[i] + bhh0[i];
        g_bias1[i] = bih1[i] + bhh1[i];
    }
}

// ------------------------- reset h buffers + barrier -------------------------
__global__ void reset_state() {
    int i = blockIdx.x * blockDim.x + threadIdx.x;
    if (i < B * H) { g_h[0][i] = 0.0f; g_h[1][i] = 0.0f; }
    if (i == 0) g_bar = 0u;
}

// ------------------------- projection GEMM -------------------------
// C[m][n] = sum_k A[m][k] * W[n][k] + bias[n],  m = t*B + b, M=T*B=32768, N=G=2048
// layer 0: A = x ([B,T,DIN], so row m -> x[(b*T+t)*DIN]), K=DIN
// layer 1: A = g_hseq (contiguous rows),                  K=H
__global__ void __launch_bounds__(256, 2) gemm_proj(const float* __restrict__ Aext, int layer)
{
    __shared__ float As[16][132];
    __shared__ float Bs[16][132];

    const float* A    = layer ? g_hseq  : Aext;
    const float* W    = layer ? g_Wih1  : g_Wih0;
    const float* bias = layer ? g_bias1 : g_bias0;
    float*       C    = g_xW;
    const int K       = layer ? H : DIN;
    const int xmode   = layer ? 0 : 1;

    const int tid = threadIdx.x;
    const int ms0 = blockIdx.y << 7;
    const int ns0 = blockIdx.x << 7;
    const int tx  = tid & 15;   // n group
    const int ty  = tid >> 4;   // m group

    u64 acc[8][4];
#pragma unroll
    for (int i = 0; i < 8; i++) {
#pragma unroll
        for (int j = 0; j < 4; j++) acc[i][j] = 0ULL;
    }

    // loader assignments: 512 float4 per tile side, 2 per thread
    int srow[2], skq[2];
    const float* aptr[2];
    const float* bptr[2];
#pragma unroll
    for (int l = 0; l < 2; l++) {
        int q = tid * 2 + l;
        srow[l] = q >> 2;
        skq[l]  = (q & 3) * 4;
        int m = ms0 + srow[l];
        const float* abase = xmode ? (A + (size_t)((m & (B - 1)) * T + (m >> 6)) * K)
                                   : (A + (size_t)m * K);
        aptr[l] = abase + skq[l];
        bptr[l] = W + (size_t)(ns0 + srow[l]) * K + skq[l];
    }

    for (int kc = 0; kc < K; kc += 16) {
        __syncthreads();
#pragma unroll
        for (int l = 0; l < 2; l++) {
            float4 av = *(const float4*)(aptr[l] + kc);
            As[skq[l] + 0][srow[l]] = av.x;
            As[skq[l] + 1][srow[l]] = av.y;
            As[skq[l] + 2][srow[l]] = av.z;
            As[skq[l] + 3][srow[l]] = av.w;
            float4 bv = *(const float4*)(bptr[l] + kc);
            Bs[skq[l] + 0][srow[l]] = bv.x;
            Bs[skq[l] + 1][srow[l]] = bv.y;
            Bs[skq[l] + 2][srow[l]] = bv.z;
            Bs[skq[l] + 3][srow[l]] = bv.w;
        }
        __syncthreads();
#pragma unroll
        for (int k = 0; k < 16; k++) {
            float4 a0 = *(const float4*)&As[k][ty * 8];
            float4 a1 = *(const float4*)&As[k][ty * 8 + 4];
            u64 b0 = *(const u64*)&Bs[k][tx * 8 + 0];
            u64 b1 = *(const u64*)&Bs[k][tx * 8 + 2];
            u64 b2 = *(const u64*)&Bs[k][tx * 8 + 4];
            u64 b3 = *(const u64*)&Bs[k][tx * 8 + 6];
            float a[8] = {a0.x, a0.y, a0.z, a0.w, a1.x, a1.y, a1.z, a1.w};
#pragma unroll
            for (int i = 0; i < 8; i++) {
                u64 av = f2pack(a[i], a[i]);
                ffma2(acc[i][0], av, b0);
                ffma2(acc[i][1], av, b1);
                ffma2(acc[i][2], av, b2);
                ffma2(acc[i][3], av, b3);
            }
        }
    }

    float bv[8];
#pragma unroll
    for (int j = 0; j < 8; j++) bv[j] = bias[ns0 + tx * 8 + j];
#pragma unroll
    for (int i = 0; i < 8; i++) {
        int m = ms0 + ty * 8 + i;
        float2 p0 = f2unpack(acc[i][0]);
        float2 p1 = f2unpack(acc[i][1]);
        float2 p2 = f2unpack(acc[i][2]);
        float2 p3 = f2unpack(acc[i][3]);
        float4 o0 = make_float4(p0.x + bv[0], p0.y + bv[1], p1.x + bv[2], p1.y + bv[3]);
        float4 o1 = make_float4(p2.x + bv[4], p2.y + bv[5], p3.x + bv[6], p3.y + bv[7]);
        *(float4*)&C[(size_t)m * G + ns0 + tx * 8]     = o0;
        *(float4*)&C[(size_t)m * G + ns0 + tx * 8 + 4] = o1;
    }
}

// ------------------------- recurrence (persistent, grid-synced) -------------------------
// 128 CTAs, each owns 4 hidden units (16 gate rows). Weights resident in SMEM.
// Double-buffered g_h so one grid barrier per step suffices.
__global__ void __launch_bounds__(RTHREADS) recur_kernel(float* outArg, int layer)
{
    extern __shared__ float sm[];
    float* Ws = sm;                       // [16][WS_STRIDE]
    float* Hs = Ws + 16 * WS_STRIDE;      // [64][HS_STRIDE]
    float* Gb = Hs + 64 * HS_STRIDE;      // [16][GB_STRIDE]

    const float* Whh  = layer ? g_Whh1 : g_Whh0;
    float*       hseq = layer ? (float*)0 : g_hseq;
    float*       outp = layer ? outArg : (float*)0;

    const int tid = threadIdx.x;
    const int j0  = blockIdx.x * 4;       // first hidden unit owned by this CTA

    // load 16 gate rows of W_hh into SMEM (row r = q*4+u -> gate row q*H + j0+u)
    for (int i = tid; i < 16 * H; i += RTHREADS) {
        int r = i >> 9, k = i & (H - 1);
        Ws[r * WS_STRIDE + k] = Whh[(size_t)((r >> 2) * H + j0 + (r & 3)) * H + k];
    }

    const int r2 = tid & 7;               // rows r2 and r2+8
    const int bp = tid >> 3;              // batch pair
    const int b0 = bp * 2;
    const int ub = tid & 3;               // activation-phase hidden-unit
    const int bb = tid >> 2;              // activation-phase batch
    const int gq0 = ((r2) >> 2) * H + j0 + ((r2) & 3);
    const int gq1 = ((r2 + 8) >> 2) * H + j0 + ((r2 + 8) & 3);
    float creg = 0.0f;                    // cell state lives in registers

    for (int t = 0; t < T; t++) {
        const float* hin  = g_h[t & 1];
        float*       hout = g_h[(t + 1) & 1];
        u64 a00 = 0ULL, a01 = 0ULL, a10 = 0ULL, a11 = 0ULL;

        for (int kc = 0; kc < H; kc += KCH) {
            __syncthreads();  // previous chunk fully consumed
            // stage h chunk (bypass L1: other CTAs wrote it)
            for (int q = tid; q < 64 * (KCH / 4); q += RTHREADS) {
                int b = q >> 5, k4 = (q & 31) << 2;
                float4 v = __ldcg((const float4*)(hin + b * H + kc + k4));
                *(float4*)&Hs[b * HS_STRIDE + k4] = v;
            }
            __syncthreads();
#pragma unroll 4
            for (int k = 0; k < KCH; k += 4) {
                float4 w0 = *(const float4*)&Ws[r2 * WS_STRIDE + kc + k];
                float4 w1 = *(const float4*)&Ws[(r2 + 8) * WS_STRIDE + kc + k];
                float4 h0 = *(const float4*)&Hs[b0 * HS_STRIDE + k];
                float4 h1 = *(const float4*)&Hs[(b0 + 1) * HS_STRIDE + k];
                u64 w0l = f2pack(w0.x, w0.y), w0h = f2pack(w0.z, w0.w);
                u64 w1l = f2pack(w1.x, w1.y), w1h = f2pack(w1.z, w1.w);
                u64 h0l = f2pack(h0.x, h0.y), h0h = f2pack(h0.z, h0.w);
                u64 h1l = f2pack(h1.x, h1.y), h1h = f2pack(h1.z, h1.w);
                ffma2(a00, w0l, h0l); ffma2(a00, w0h, h0h);
                ffma2(a01, w0l, h1l); ffma2(a01, w0h, h1h);
                ffma2(a10, w1l, h0l); ffma2(a10, w1h, h0h);
                ffma2(a11, w1l, h1l); ffma2(a11, w1h, h1h);
            }
        }

        const float* xwt = g_xW + (size_t)t * B * G;
        float2 s;
        s = f2unpack(a00); Gb[r2 * GB_STRIDE + b0]           = s.x + s.y + xwt[(b0)     * G + gq0];
        s = f2unpack(a01); Gb[r2 * GB_STRIDE + b0 + 1]       = s.x + s.y + xwt[(b0 + 1) * G + gq0];
        s = f2unpack(a10); Gb[(r2 + 8) * GB_STRIDE + b0]     = s.x + s.y + xwt[(b0)     * G + gq1];
        s = f2unpack(a11); Gb[(r2 + 8) * GB_STRIDE + b0 + 1] = s.x + s.y + xwt[(b0 + 1) * G + gq1];
        __syncthreads();

        float iv = Gb[(0  + ub) * GB_STRIDE + bb];
        float fv = Gb[(4  + ub) * GB_STRIDE + bb];
        float gv = Gb[(8  + ub) * GB_STRIDE + bb];
        float ov = Gb[(12 + ub) * GB_STRIDE + bb];
        creg = sigmf(fv) * creg + sigmf(iv) * tanhf(gv);
        float hv = sigmf(ov) * tanhf(creg);

        hout[bb * H + j0 + ub] = hv;
        if (hseq) hseq[(size_t)(t * B + bb) * H + j0 + ub] = hv;
        if (outp && t == T - 1) outp[bb * H + j0 + ub] = hv;

        if (t + 1 < T) {
            __threadfence();
            __syncthreads();
            if (tid == 0) {
                atomicAdd(&g_bar, 1u);
                unsigned int want = (unsigned int)(t + 1) * (unsigned int)NCTA;
                unsigned int v;
                do {
                    asm volatile("ld.acquire.gpu.global.u32 %0, [%1];"
                                 : "=r"(v) : "l"(&g_bar));
                } while (v < want);
            }
            __syncthreads();
        }
    }
}

// ------------------------- launch -------------------------
extern "C" void kernel_launch(void* const* d_in, const int* in_sizes, int n_in,
                              void* d_out, int out_size)
{
    (void)in_sizes; (void)n_in; (void)out_size;
    const float* x = (const float*)d_in[0];

    cudaFuncSetAttribute(recur_kernel, cudaFuncAttributeMaxDynamicSharedMemorySize, RECUR_SMEM);

    prep_kernel<<<512, 256>>>(
        (const float*)d_in[1],  (const float*)d_in[5],
        (const float*)d_in[2],  (const float*)d_in[6],
        (const float*)d_in[3],  (const float*)d_in[4],
        (const float*)d_in[7],  (const float*)d_in[11],
        (const float*)d_in[8],  (const float*)d_in[12],
        (const float*)d_in[9],  (const float*)d_in[10]);

    dim3 pgrid(G / 128, (T * B) / 128);

    // layer 0
    gemm_proj<<<pgrid, 256>>>(x, 0);
    reset_state<<<(B * H + 255) / 256, 256>>>();
    recur_kernel<<<NCTA, RTHREADS, RECUR_SMEM>>>((float*)0, 0);

    // layer 1
    gemm_proj<<<pgrid, 256>>>((const float*)0, 1);
    reset_state<<<(B * H + 255) / 256, 256>>>();
    recur_kernel<<<NCTA, RTHREADS, RECUR_SMEM>>>((float*)d_out, 1);
}

// round 2
// speedup vs baseline: 1.6217x; 1.6217x over previous
#include <cuda_runtime.h>

// Problem constants
#define B    64
#define T    512
#define DIN  256
#define H    512
#define G    2048   // 4*H

#define NCTA      128
#define RTHREADS  256

// recurrence v2 layout
#define GROUPB    8                        // batches staged per group
#define NGRP      (B / GROUPB)             // 8
#define HB_STRIDE 72                       // floats per batch row in hbuf (64 + pad, halves at +0/+36)
#define HBUF_WARP (GROUPB * HB_STRIDE)     // 576 floats per warp per buffer
#define P_STRIDE  20                       // floats per (row) slot in partial (16 + pad)
#define PB_STRIDE 324                      // floats per batch in partial (16*20 + 4 pad)
#define RECUR2_SMEM ((8 * 2 * HBUF_WARP + B * PB_STRIDE) * 4)

typedef unsigned long long u64;

// ------------------------- device scratch -------------------------
__device__ float g_Wih0[G * DIN];
__device__ float g_Whh0[G * H];
__device__ float g_Wih1[G * H];
__device__ float g_Whh1[G * H];
__device__ float g_bias0[G];
__device__ float g_bias1[G];
__device__ float g_xW[(size_t)T * B * G];     // [t*B+b][G]
__device__ float g_hseq[(size_t)T * B * H];   // [t*B+b][H]
__device__ float g_h[2][B * H];               // double-buffered hidden state
__device__ unsigned int g_bar;

// ------------------------- helpers -------------------------
__device__ __forceinline__ u64 f2pack(float x, float y) {
    u64 r; asm("mov.b64 %0, {%1, %2};" : "=l"(r) : "f"(x), "f"(y)); return r;
}
__device__ __forceinline__ float2 f2unpack(u64 v) {
    float2 r; asm("mov.b64 {%0, %1}, %2;" : "=f"(r.x), "=f"(r.y) : "l"(v)); return r;
}
__device__ __forceinline__ void ffma2(u64& d, u64 a, u64 b) {
    asm("fma.rn.f32x2 %0, %1, %2, %0;" : "+l"(d) : "l"(a), "l"(b));
}
__device__ __forceinline__ float sigmf(float x) {
    return 1.0f / (1.0f + __expf(-x));
}

// ------------------------- prep -------------------------
__global__ void prep_kernel(const float* Wih0, const float* mih0,
                            const float* Whh0, const float* mhh0,
                            const float* bih0, const float* bhh0,
                            const float* Wih1, const float* mih1,
                            const float* Whh1, const float* mhh1,
                            const float* bih1, const float* bhh1)
{
    int idx0 = blockIdx.x * blockDim.x + threadIdx.x;
    int stride = gridDim.x * blockDim.x;
    for (int i = idx0; i < G * DIN; i += stride) g_Wih0[i] = Wih0[i] * mih0[i];
    for (int i = idx0; i < G * H;  i += stride) g_Whh0[i] = Whh0[i] * mhh0[i];
    for (int i = idx0; i < G * H;  i += stride) g_Wih1[i] = Wih1[i] * mih1[i];
    for (int i = idx0; i < G * H;  i += stride) g_Whh1[i] = Whh1[i] * mhh1[i];
    for (int i = idx0; i < G;      i += stride) {
        g_bias0[i] = bih0[i] + bhh0[i];
        g_bias1[i] = bih1[i] + bhh1[i];
    }
}

__global__ void reset_state() {
    int i = blockIdx.x * blockDim.x + threadIdx.x;
    if (i < B * H) { g_h[0][i] = 0.0f; g_h[1][i] = 0.0f; }
    if (i == 0) g_bar = 0u;
}

// ------------------------- projection GEMM (unchanged from R1) -------------------------
__global__ void __launch_bounds__(256, 2) gemm_proj(const float* __restrict__ Aext, int layer)
{
    __shared__ float As[16][132];
    __shared__ float Bs[16][132];

    const float* A    = layer ? g_hseq  : Aext;
    const float* W    = layer ? g_Wih1  : g_Wih0;
    const float* bias = layer ? g_bias1 : g_bias0;
    float*       C    = g_xW;
    const int K       = layer ? H : DIN;
    const int xmode   = layer ? 0 : 1;

    const int tid = threadIdx.x;
    const int ms0 = blockIdx.y << 7;
    const int ns0 = blockIdx.x << 7;
    const int tx  = tid & 15;
    const int ty  = tid >> 4;

    u64 acc[8][4];
#pragma unroll
    for (int i = 0; i < 8; i++)
#pragma unroll
        for (int j = 0; j < 4; j++) acc[i][j] = 0ULL;

    int srow[2], skq[2];
    const float* aptr[2];
    const float* bptr[2];
#pragma unroll
    for (int l = 0; l < 2; l++) {
        int q = tid * 2 + l;
        srow[l] = q >> 2;
        skq[l]  = (q & 3) * 4;
        int m = ms0 + srow[l];
        const float* abase = xmode ? (A + (size_t)((m & (B - 1)) * T + (m >> 6)) * K)
                                   : (A + (size_t)m * K);
        aptr[l] = abase + skq[l];
        bptr[l] = W + (size_t)(ns0 + srow[l]) * K + skq[l];
    }

    for (int kc = 0; kc < K; kc += 16) {
        __syncthreads();
#pragma unroll
        for (int l = 0; l < 2; l++) {
            float4 av = *(const float4*)(aptr[l] + kc);
            As[skq[l] + 0][srow[l]] = av.x;
            As[skq[l] + 1][srow[l]] = av.y;
            As[skq[l] + 2][srow[l]] = av.z;
            As[skq[l] + 3][srow[l]] = av.w;
            float4 bv = *(const float4*)(bptr[l] + kc);
            Bs[skq[l] + 0][srow[l]] = bv.x;
            Bs[skq[l] + 1][srow[l]] = bv.y;
            Bs[skq[l] + 2][srow[l]] = bv.z;
            Bs[skq[l] + 3][srow[l]] = bv.w;
        }
        __syncthreads();
#pragma unroll
        for (int k = 0; k < 16; k++) {
            float4 a0 = *(const float4*)&As[k][ty * 8];
            float4 a1 = *(const float4*)&As[k][ty * 8 + 4];
            u64 b0 = *(const u64*)&Bs[k][tx * 8 + 0];
            u64 b1 = *(const u64*)&Bs[k][tx * 8 + 2];
            u64 b2 = *(const u64*)&Bs[k][tx * 8 + 4];
            u64 b3 = *(const u64*)&Bs[k][tx * 8 + 6];
            float a[8] = {a0.x, a0.y, a0.z, a0.w, a1.x, a1.y, a1.z, a1.w};
#pragma unroll
            for (int i = 0; i < 8; i++) {
                u64 av = f2pack(a[i], a[i]);
                ffma2(acc[i][0], av, b0);
                ffma2(acc[i][1], av, b1);
                ffma2(acc[i][2], av, b2);
                ffma2(acc[i][3], av, b3);
            }
        }
    }

    float bv[8];
#pragma unroll
    for (int j = 0; j < 8; j++) bv[j] = bias[ns0 + tx * 8 + j];
#pragma unroll
    for (int i = 0; i < 8; i++) {
        int m = ms0 + ty * 8 + i;
        float2 p0 = f2unpack(acc[i][0]);
        float2 p1 = f2unpack(acc[i][1]);
        float2 p2 = f2unpack(acc[i][2]);
        float2 p3 = f2unpack(acc[i][3]);
        float4 o0 = make_float4(p0.x + bv[0], p0.y + bv[1], p1.x + bv[2], p1.y + bv[3]);
        float4 o1 = make_float4(p2.x + bv[4], p2.y + bv[5], p3.x + bv[6], p3.y + bv[7]);
        *(float4*)&C[(size_t)m * G + ns0 + tx * 8]     = o0;
        *(float4*)&C[(size_t)m * G + ns0 + tx * 8 + 4] = o1;
    }
}

// ------------------------- recurrence v2 -------------------------
// 128 CTAs * 4 hidden units. W_hh slice register-resident per lane
// (lane = (row 16) x (k-half 2), warp owns 64-k slice of K=512).
// h staged warp-locally in 8-batch groups, double-buffered, prefetch overlapped.
__global__ void __launch_bounds__(RTHREADS) recur_kernel(float* outArg, int layer)
{
    extern __shared__ float sm[];
    float* hbuf = sm;                         // [8 warps][2 bufs][GROUPB][HB_STRIDE]
    float* part = sm + 8 * 2 * HBUF_WARP;     // [B][PB_STRIDE]

    const float* Whh  = layer ? g_Whh1 : g_Whh0;
    float*       hseq = layer ? (float*)0 : g_hseq;
    float*       outp = layer ? outArg : (float*)0;

    const int tid = threadIdx.x;
    const int w   = tid >> 5;
    const int ln  = tid & 31;
    const int r   = ln & 15;                  // local gate row (gate = r>>2, unit = r&3)
    const int hf  = ln >> 4;                  // k-half within warp slice
    const int j0  = blockIdx.x * 4;
    const int p   = w * 2 + hf;               // partial index 0..15

    // ---- load W_hh slice into registers (held across all timesteps) ----
    u64 wreg[16];
    {
        const int grow = (r >> 2) * H + j0 + (r & 3);
        const float* wp = Whh + (size_t)grow * H + w * 64 + hf * 32;
#pragma unroll
        for (int i = 0; i < 8; i++) {
            float4 v = __ldg((const float4*)(wp + i * 4));
            wreg[2 * i]     = f2pack(v.x, v.y);
            wreg[2 * i + 1] = f2pack(v.z, v.w);
        }
    }

    // ---- precomputed staging offsets (per lane) ----
    int g_off[4], s_off[4];
#pragma unroll
    for (int i = 0; i < 4; i++) {
        int idx = i * 32 + ln;
        int b   = idx >> 4;       // batch within group
        int kq  = idx & 15;       // float4 within 64-k slice
        g_off[i] = b * H + w * 64 + kq * 4;
        s_off[i] = b * HB_STRIDE + kq * 4 + ((kq >> 3) << 2);  // halves at +0 / +36
    }
    float* mybuf[2] = { hbuf + (w * 2 + 0) * HBUF_WARP,
                        hbuf + (w * 2 + 1) * HBUF_WARP };

    const int u  = tid & 3;       // activation-phase unit
    const int bb = tid >> 2;      // activation-phase batch
    float creg = 0.0f;

    for (int t = 0; t < T; t++) {
        const float* hin  = g_h[t & 1];
        float*       hout = g_h[(t + 1) & 1];
        const float* xwt  = g_xW + (size_t)t * B * G;

        // prefetch xW gates for the activation phase
        float xg[4];
#pragma unroll
        for (int g = 0; g < 4; g++)
            xg[g] = __ldg(&xwt[bb * G + g * H + j0 + u]);

        // stage group 0
        float4 sreg[4];
#pragma unroll
        for (int i = 0; i < 4; i++)
            sreg[i] = __ldcg((const float4*)(hin + g_off[i]));
#pragma unroll
        for (int i = 0; i < 4; i++)
            *(float4*)(mybuf[0] + s_off[i]) = sreg[i];
        __syncwarp();

        for (int g = 0; g < NGRP; g++) {
            if (g + 1 < NGRP) {
                const float* src = hin + (g + 1) * GROUPB * H;
#pragma unroll
                for (int i = 0; i < 4; i++)
                    sreg[i] = __ldcg((const float4*)(src + g_off[i]));
            }
            const float* bc = mybuf[g & 1];
#pragma unroll 2
            for (int b2 = 0; b2 < GROUPB; b2++) {
                const float* hp = bc + b2 * HB_STRIDE + hf * 36;
                u64 a0 = 0ULL, a1 = 0ULL;
#pragma unroll
                for (int i = 0; i < 8; i++) {
                    float4 hv = *(const float4*)(hp + i * 4);
                    ffma2(a0, wreg[2 * i],     f2pack(hv.x, hv.y));
                    ffma2(a1, wreg[2 * i + 1], f2pack(hv.z, hv.w));
                }
                float2 s0 = f2unpack(a0), s1 = f2unpack(a1);
                part[(g * GROUPB + b2) * PB_STRIDE + r * P_STRIDE + p] =
                    (s0.x + s0.y) + (s1.x + s1.y);
            }
            if (g + 1 < NGRP) {
                float* bn = mybuf[(g + 1) & 1];
#pragma unroll
                for (int i = 0; i < 4; i++)
                    *(float4*)(bn + s_off[i]) = sreg[i];
                __syncwarp();
            }
        }
        __syncthreads();

        // ---- activation: thread (u, bb) handles one (unit, batch) cell ----
        float gate[4];
#pragma unroll
        for (int g = 0; g < 4; g++) {
            const float* pp = part + bb * PB_STRIDE + (g * 4 + u) * P_STRIDE;
            float4 q0 = *(const float4*)(pp);
            float4 q1 = *(const float4*)(pp + 4);
            float4 q2 = *(const float4*)(pp + 8);
            float4 q3 = *(const float4*)(pp + 12);
            gate[g] = (((q0.x + q0.y) + (q0.z + q0.w)) + ((q1.x + q1.y) + (q1.z + q1.w)))
                    + (((q2.x + q2.y) + (q2.z + q2.w)) + ((q3.x + q3.y) + (q3.z + q3.w)))
                    + xg[g];
        }
        creg = sigmf(gate[1]) * creg + sigmf(gate[0]) * __tanhf(gate[2]);
        float hv = sigmf(gate[3]) * __tanhf(creg);

        __stcg(&hout[bb * H + j0 + u], hv);
        if (hseq) hseq[(size_t)(t * B + bb) * H + j0 + u] = hv;
        if (outp && t == T - 1) outp[bb * H + j0 + u] = hv;

        // ---- grid barrier ----
        if (t + 1 < T) {
            __syncthreads();      // also protects 'part' reuse
            if (tid == 0) {
                unsigned int one = 1u;
                asm volatile("red.release.gpu.global.add.u32 [%0], %1;"
                             :: "l"(&g_bar), "r"(one) : "memory");
                unsigned int want = (unsigned int)(t + 1) * (unsigned int)NCTA;
                unsigned int v;
                do {
                    asm volatile("ld.acquire.gpu.global.u32 %0, [%1];"
                                 : "=r"(v) : "l"(&g_bar));
                } while (v < want);
            }
            __syncthreads();
        }
    }
}

// ------------------------- launch -------------------------
extern "C" void kernel_launch(void* const* d_in, const int* in_sizes, int n_in,
                              void* d_out, int out_size)
{
    (void)in_sizes; (void)n_in; (void)out_size;
    const float* x = (const float*)d_in[0];

    cudaFuncSetAttribute(recur_kernel, cudaFuncAttributeMaxDynamicSharedMemorySize, RECUR2_SMEM);

    prep_kernel<<<512, 256>>>(
        (const float*)d_in[1],  (const float*)d_in[5],
        (const float*)d_in[2],  (const float*)d_in[6],
        (const float*)d_in[3],  (const float*)d_in[4],
        (const float*)d_in[7],  (const float*)d_in[11],
        (const float*)d_in[8],  (const float*)d_in[12],
        (const float*)d_in[9],  (const float*)d_in[10]);

    dim3 pgrid(G / 128, (T * B) / 128);

    // layer 0
    gemm_proj<<<pgrid, 256>>>(x, 0);
    reset_state<<<(B * H + 255) / 256, 256>>>();
    recur_kernel<<<NCTA, RTHREADS, RECUR2_SMEM>>>((float*)0, 0);

    // layer 1
    gemm_proj<<<pgrid, 256>>>((const float*)0, 1);
    reset_state<<<(B * H + 255) / 256, 256>>>();
    recur_kernel<<<NCTA, RTHREADS, RECUR2_SMEM>>>((float*)d_out, 1);
}

// round 3
// speedup vs baseline: 1.7150x; 1.0575x over previous
#include <cuda_runtime.h>

// Problem constants
#define B    64
#define T    512
#define DIN  256
#define H    512
#define G    2048   // 4*H

#define NCTA      128
#define RTHREADS  256

// recurrence v3 SMEM layout (floats)
#define WPAD   516                       // W row stride (512 + 4)
#define HPAD   132                       // h chunk row stride (128 + 4)
#define PPAD   20                        // partial row stride (16 + 4)
#define WS_TOT (32 * WPAD)               // 16512
#define HB_TOT (2 * 32 * HPAD)           // 8448
#define PT_TOT (8 * 32 * PPAD)           // 5120
#define HV_TOT (32 * 12)                 // 384
#define RECUR3_SMEM ((WS_TOT + HB_TOT + PT_TOT + HV_TOT) * 4)

typedef unsigned long long u64;

// ------------------------- device scratch -------------------------
__device__ float g_Wih0[G * DIN];
__device__ float g_Whh0[G * H];
__device__ float g_Wih1[G * H];
__device__ float g_Whh1[G * H];
__device__ float g_bias0[G];
__device__ float g_bias1[G];
__device__ float g_xW[(size_t)T * B * G];     // [t*B+b][G]
__device__ float g_hseq[(size_t)T * B * H];   // [t*B+b][H]  (layer0 h output, also its h state)
__device__ float g_h[2][B * H];               // layer1 double-buffered hidden state (g_h[0] also = zeros for t=0)
__device__ unsigned int g_bar;

// ------------------------- helpers -------------------------
__device__ __forceinline__ u64 f2pack(float x, float y) {
    u64 r; asm("mov.b64 %0, {%1, %2};" : "=l"(r) : "f"(x), "f"(y)); return r;
}
__device__ __forceinline__ float2 f2unpack(u64 v) {
    float2 r; asm("mov.b64 {%0, %1}, %2;" : "=f"(r.x), "=f"(r.y) : "l"(v)); return r;
}
__device__ __forceinline__ void ffma2(u64& d, u64 a, u64 b) {
    asm("fma.rn.f32x2 %0, %1, %2, %0;" : "+l"(d) : "l"(a), "l"(b));
}
__device__ __forceinline__ float sigmf(float x) {
    return 1.0f / (1.0f + __expf(-x));
}

// ------------------------- prep -------------------------
__global__ void prep_kernel(const float* Wih0, const float* mih0,
                            const float* Whh0, const float* mhh0,
                            const float* bih0, const float* bhh0,
                            const float* Wih1, const float* mih1,
                            const float* Whh1, const float* mhh1,
                            const float* bih1, const float* bhh1)
{
    int idx0 = blockIdx.x * blockDim.x + threadIdx.x;
    int stride = gridDim.x * blockDim.x;
    for (int i = idx0; i < G * DIN; i += stride) g_Wih0[i] = Wih0[i] * mih0[i];
    for (int i = idx0; i < G * H;  i += stride) g_Whh0[i] = Whh0[i] * mhh0[i];
    for (int i = idx0; i < G * H;  i += stride) g_Wih1[i] = Wih1[i] * mih1[i];
    for (int i = idx0; i < G * H;  i += stride) g_Whh1[i] = Whh1[i] * mhh1[i];
    for (int i = idx0; i < G;      i += stride) {
        g_bias0[i] = bih0[i] + bhh0[i];
        g_bias1[i] = bih1[i] + bhh1[i];
    }
}

__global__ void reset_state() {
    int i = blockIdx.x * blockDim.x + threadIdx.x;
    if (i < B * H) { g_h[0][i] = 0.0f; g_h[1][i] = 0.0f; }
    if (i == 0) g_bar = 0u;
}

// ------------------------- projection GEMM (unchanged) -------------------------
__global__ void __launch_bounds__(256, 2) gemm_proj(const float* __restrict__ Aext, int layer)
{
    __shared__ float As[16][132];
    __shared__ float Bs[16][132];

    const float* A    = layer ? g_hseq  : Aext;
    const float* W    = layer ? g_Wih1  : g_Wih0;
    const float* bias = layer ? g_bias1 : g_bias0;
    float*       C    = g_xW;
    const int K       = layer ? H : DIN;
    const int xmode   = layer ? 0 : 1;

    const int tid = threadIdx.x;
    const int ms0 = blockIdx.y << 7;
    const int ns0 = blockIdx.x << 7;
    const int tx  = tid & 15;
    const int ty  = tid >> 4;

    u64 acc[8][4];
#pragma unroll
    for (int i = 0; i < 8; i++)
#pragma unroll
        for (int j = 0; j < 4; j++) acc[i][j] = 0ULL;

    int srow[2], skq[2];
    const float* aptr[2];
    const float* bptr[2];
#pragma unroll
    for (int l = 0; l < 2; l++) {
        int q = tid * 2 + l;
        srow[l] = q >> 2;
        skq[l]  = (q & 3) * 4;
        int m = ms0 + srow[l];
        const float* abase = xmode ? (A + (size_t)((m & (B - 1)) * T + (m >> 6)) * K)
                                   : (A + (size_t)m * K);
        aptr[l] = abase + skq[l];
        bptr[l] = W + (size_t)(ns0 + srow[l]) * K + skq[l];
    }

    for (int kc = 0; kc < K; kc += 16) {
        __syncthreads();
#pragma unroll
        for (int l = 0; l < 2; l++) {
            float4 av = *(const float4*)(aptr[l] + kc);
            As[skq[l] + 0][srow[l]] = av.x;
            As[skq[l] + 1][srow[l]] = av.y;
            As[skq[l] + 2][srow[l]] = av.z;
            As[skq[l] + 3][srow[l]] = av.w;
            float4 bv = *(const float4*)(bptr[l] + kc);
            Bs[skq[l] + 0][srow[l]] = bv.x;
            Bs[skq[l] + 1][srow[l]] = bv.y;
            Bs[skq[l] + 2][srow[l]] = bv.z;
            Bs[skq[l] + 3][srow[l]] = bv.w;
        }
        __syncthreads();
#pragma unroll
        for (int k = 0; k < 16; k++) {
            float4 a0 = *(const float4*)&As[k][ty * 8];
            float4 a1 = *(const float4*)&As[k][ty * 8 + 4];
            u64 b0 = *(const u64*)&Bs[k][tx * 8 + 0];
            u64 b1 = *(const u64*)&Bs[k][tx * 8 + 2];
            u64 b2 = *(const u64*)&Bs[k][tx * 8 + 4];
            u64 b3 = *(const u64*)&Bs[k][tx * 8 + 6];
            float a[8] = {a0.x, a0.y, a0.z, a0.w, a1.x, a1.y, a1.z, a1.w};
#pragma unroll
            for (int i = 0; i < 8; i++) {
                u64 av = f2pack(a[i], a[i]);
                ffma2(acc[i][0], av, b0);
                ffma2(acc[i][1], av, b1);
                ffma2(acc[i][2], av, b2);
                ffma2(acc[i][3], av, b3);
            }
        }
    }

    float bv[8];
#pragma unroll
    for (int j = 0; j < 8; j++) bv[j] = bias[ns0 + tx * 8 + j];
#pragma unroll
    for (int i = 0; i < 8; i++) {
        int m = ms0 + ty * 8 + i;
        float2 p0 = f2unpack(acc[i][0]);
        float2 p1 = f2unpack(acc[i][1]);
        float2 p2 = f2unpack(acc[i][2]);
        float2 p3 = f2unpack(acc[i][3]);
        float4 o0 = make_float4(p0.x + bv[0], p0.y + bv[1], p1.x + bv[2], p1.y + bv[3]);
        float4 o1 = make_float4(p2.x + bv[4], p2.y + bv[5], p3.x + bv[6], p3.y + bv[7]);
        *(float4*)&C[(size_t)m * G + ns0 + tx * 8]     = o0;
        *(float4*)&C[(size_t)m * G + ns0 + tx * 8 + 4] = o1;
    }
}

// ------------------------- recurrence v3 -------------------------
// CTA = 8 units x 32 batches (64 unit-tiles x 2 batch-halves = 128 CTAs).
// warp (ug,kq) = 4 units x 32 batches(lane) x 128-k interleaved quarter.
// W broadcast from SMEM, h as ulonglong2 k-pairs, 16 private accs/lane,
// one 4-way cross-warp reduction per STEP, c resident per activation thread.
__global__ void __launch_bounds__(RTHREADS) recur_kernel(float* outArg, int layer)
{
    extern __shared__ float sm[];
    float* Ws   = sm;                                // [32 rows][WPAD]
    float* hb   = Ws + WS_TOT;                       // [2][32 b][HPAD]
    float* part = hb + HB_TOT;                       // [8 w][32 b][PPAD]
    float* hvb  = part + PT_TOT;                     // [32 b][12]

    const float* Whh = layer ? g_Whh1 : g_Whh0;
    const int tid = threadIdx.x;
    const int w   = tid >> 5;
    const int ln  = tid & 31;
    const int ug  = w >> 2;          // unit group 0/1
    const int kq  = w & 3;           // k-quarter phase
    const int uTile = blockIdx.x >> 1;
    const int bh    = blockIdx.x & 1;
    const int unit0 = uTile * 8;
    const int bb0   = bh * 32;

    // ---- stage masked W_hh rows into SMEM (row r = u_cta*4 + gate) ----
    for (int i = tid; i < 32 * 128; i += RTHREADS) {
        int r   = i >> 7;          // 0..31
        int kc4 = i & 127;
        int u   = r >> 2, g = r & 3;
        float4 v = __ldg((const float4*)(Whh + (size_t)(g * H + unit0 + u) * H + kc4 * 4));
        *(float4*)&Ws[r * WPAD + kc4 * 4] = v;
    }
    __syncthreads();

    // per-warp W base (4 units of this ug)
    const float* Wwarp = Ws + (ug * 4) * 4 * WPAD;
    float* hrow0 = hb + ln * HPAD;                   // buffer 0 row for this lane(batch)
    float* hrow1 = hb + 32 * HPAD + ln * HPAD;

    // staging roles
    const int sb = tid >> 5;            // 0..7 batch sub
    const int sk = (tid & 31) * 4;      // k float offset within 128-chunk

    // activation roles
    const int ul = tid >> 5;            // unit 0..7
    const int ab = tid & 31;            // batch 0..31
    float creg = 0.0f;

    float* hseq = layer ? (float*)0 : g_hseq;
    float* outp = layer ? outArg : (float*)0;

    for (int t = 0; t < T; t++) {
        const float* hin;
        if (layer == 0) hin = (t == 0) ? g_h[0] : (g_hseq + (size_t)(t - 1) * B * H);
        else            hin = g_h[t & 1];
        float* hout = layer ? g_h[(t + 1) & 1] : (g_hseq + (size_t)t * B * H);
        const float* xwt = g_xW + (size_t)t * B * G;

        // prefetch xW gates for activation phase
        float xg0 = __ldg(&xwt[(bb0 + ab) * G + 0 * H + unit0 + ul]);
        float xg1 = __ldg(&xwt[(bb0 + ab) * G + 1 * H + unit0 + ul]);
        float xg2 = __ldg(&xwt[(bb0 + ab) * G + 2 * H + unit0 + ul]);
        float xg3 = __ldg(&xwt[(bb0 + ab) * G + 3 * H + unit0 + ul]);

        u64 acc[4][4];
#pragma unroll
        for (int u = 0; u < 4; u++)
#pragma unroll
            for (int g = 0; g < 4; g++) acc[u][g] = 0ULL;

        // stage chunk 0
        float4 sreg[4];
#pragma unroll
        for (int p = 0; p < 4; p++)
            sreg[p] = __ldcg((const float4*)(hin + (size_t)(bb0 + p * 8 + sb) * H + sk));
#pragma unroll
        for (int p = 0; p < 4; p++)
            *(float4*)&hb[(p * 8 + sb) * HPAD + sk] = sreg[p];
        __syncthreads();

        for (int c = 0; c < 4; c++) {
            if (c < 3) {
                const float* src = hin + (c + 1) * 128;
#pragma unroll
                for (int p = 0; p < 4; p++)
                    sreg[p] = __ldcg((const float4*)(src + (size_t)(bb0 + p * 8 + sb) * H + sk));
            }
            // compute chunk c: 8 interleaved k4 blocks for this warp
            const float* hc = ((c & 1) ? hrow1 : hrow0);
            const float* wc = Wwarp + c * 128;
#pragma unroll
            for (int i = 0; i < 8; i++) {
                int off = (kq + 4 * i) * 4;
                ulonglong2 hp = *(const ulonglong2*)(hc + off);
                const float* wk = wc + off;
#pragma unroll
                for (int u = 0; u < 4; u++) {
#pragma unroll
                    for (int g = 0; g < 4; g++) {
                        ulonglong2 wp = *(const ulonglong2*)(wk + (u * 4 + g) * WPAD);
                        ffma2(acc[u][g], wp.x, hp.x);
                        ffma2(acc[u][g], wp.y, hp.y);
                    }
                }
            }
            if (c < 3) {
                float* dst = hb + ((c + 1) & 1) * 32 * HPAD;
#pragma unroll
                for (int p = 0; p < 4; p++)
                    *(float4*)&dst[(p * 8 + sb) * HPAD + sk] = sreg[p];
                __syncthreads();
            }
        }

        // ---- per-lane horizontal sums -> partials ----
        float* pp = part + (w * 32 + ln) * PPAD;
#pragma unroll
        for (int u = 0; u < 4; u++) {
            float2 s0 = f2unpack(acc[u][0]);
            float2 s1 = f2unpack(acc[u][1]);
            float2 s2 = f2unpack(acc[u][2]);
            float2 s3 = f2unpack(acc[u][3]);
            *(float4*)(pp + u * 4) = make_float4(s0.x + s0.y, s1.x + s1.y,
                                                 s2.x + s2.y, s3.x + s3.y);
        }
        __syncthreads();

        // ---- activation: thread = (unit ul, batch ab) ----
        {
            int wb = (ul >> 2) * 4;       // warp group for this unit
            int us = (ul & 3) * 4;
            float4 v0 = *(const float4*)(part + ((wb + 0) * 32 + ab) * PPAD + us);
            float4 v1 = *(const float4*)(part + ((wb + 1) * 32 + ab) * PPAD + us);
            float4 v2 = *(const float4*)(part + ((wb + 2) * 32 + ab) * PPAD + us);
            float4 v3 = *(const float4*)(part + ((wb + 3) * 32 + ab) * PPAD + us);
            float gi = (v0.x + v1.x) + (v2.x + v3.x) + xg0;
            float gf = (v0.y + v1.y) + (v2.y + v3.y) + xg1;
            float gg = (v0.z + v1.z) + (v2.z + v3.z) + xg2;
            float go = (v0.w + v1.w) + (v2.w + v3.w) + xg3;
            creg = sigmf(gf) * creg + sigmf(gi) * __tanhf(gg);
            float hv = sigmf(go) * __tanhf(creg);
            hvb[ab * 12 + ul] = hv;
        }
        __syncthreads();

        // ---- write h (coalesced-ish float4) ----
        if (tid < 64) {
            int b  = tid >> 1;
            int hf = tid & 1;
            float4 v = *(const float4*)&hvb[b * 12 + hf * 4];
            __stcg((float4*)(hout + (size_t)(bb0 + b) * H + unit0 + hf * 4), v);
            if (outp && t == T - 1)
                __stcg((float4*)(outp + (size_t)(bb0 + b) * H + unit0 + hf * 4), v);
        }

        // ---- grid barrier ----
        if (t + 1 < T) {
            __syncthreads();
            if (tid == 0) {
                unsigned int one = 1u;
                asm volatile("red.release.gpu.global.add.u32 [%0], %1;"
                             :: "l"(&g_bar), "r"(one) : "memory");
                unsigned int want = (unsigned int)(t + 1) * (unsigned int)NCTA;
                unsigned int v;
                do {
                    asm volatile("ld.acquire.gpu.global.u32 %0, [%1];"
                                 : "=r"(v) : "l"(&g_bar));
                } while (v < want);
            }
            __syncthreads();
        }
    }
}

// ------------------------- launch -------------------------
extern "C" void kernel_launch(void* const* d_in, const int* in_sizes, int n_in,
                              void* d_out, int out_size)
{
    (void)in_sizes; (void)n_in; (void)out_size;
    const float* x = (const float*)d_in[0];

    cudaFuncSetAttribute(recur_kernel, cudaFuncAttributeMaxDynamicSharedMemorySize, RECUR3_SMEM);

    prep_kernel<<<512, 256>>>(
        (const float*)d_in[1],  (const float*)d_in[5],
        (const float*)d_in[2],  (const float*)d_in[6],
        (const float*)d_in[3],  (const float*)d_in[4],
        (const float*)d_in[7],  (const float*)d_in[11],
        (const float*)d_in[8],  (const float*)d_in[12],
        (const float*)d_in[9],  (const float*)d_in[10]);

    dim3 pgrid(G / 128, (T * B) / 128);

    // layer 0
    gemm_proj<<<pgrid, 256>>>(x, 0);
    reset_state<<<(B * H + 255) / 256, 256>>>();
    recur_kernel<<<NCTA, RTHREADS, RECUR3_SMEM>>>((float*)0, 0);

    // layer 1
    gemm_proj<<<pgrid, 256>>>((const float*)0, 1);
    reset_state<<<(B * H + 255) / 256, 256>>>();
    recur_kernel<<<NCTA, RTHREADS, RECUR3_SMEM>>>((float*)d_out, 1);
}